// round 3
// baseline (speedup 1.0000x reference)
#include <cuda_runtime.h>
#include <math.h>

#define BB 2
#define LL 320
#define DD 128
#define DP 64
#define NH 8
#define DH 16
#define DO 32
#define NROW (BB*LL)          // 640
#define NPAIR (BB*LL*LL)      // 204800

// ---------------- scratch (allocation-free, device-side references ONLY) ----------------
__device__ float g_xn[NROW*DD];
__device__ float g_q [NROW*DD];
__device__ float g_k [NROW*DD];
__device__ float g_v [NROW*DD];
__device__ float g_bias[NPAIR*NH];     // [b,i,j,h]
__device__ float g_attn[NROW*DD];
__device__ float g_x1[NROW*DD];
__device__ float g_h [NROW*4*DD];
__device__ float g_p1[NROW*DO];
__device__ float g_p2[NROW*DO];
__device__ float g_A [NROW*DO*DP];     // [row, d, p] = 640*2048

__device__ __forceinline__ float warp_sum(float v) {
    #pragma unroll
    for (int o = 16; o; o >>= 1) v += __shfl_xor_sync(0xffffffffu, v, o);
    return v;
}
__device__ __forceinline__ float warp_max(float v) {
    #pragma unroll
    for (int o = 16; o; o >>= 1) v = fmaxf(v, __shfl_xor_sync(0xffffffffu, v, o));
    return v;
}

// ---------------- LayerNorm over 128 (device-inline, one row per block) ----------------
__device__ __forceinline__ void ln128_body(const float* __restrict__ in, float* __restrict__ out,
                                           const float* __restrict__ g, const float* __restrict__ b) {
    int row = blockIdx.x, t = threadIdx.x;
    float v = in[row*DD + t];
    __shared__ float r1[4], r2[4];
    float s = warp_sum(v);
    if ((t & 31) == 0) r1[t >> 5] = s;
    __syncthreads();
    float mu = (r1[0] + r1[1] + r1[2] + r1[3]) * (1.f/128.f);
    float d = v - mu;
    float sq = warp_sum(d*d);
    if ((t & 31) == 0) r2[t >> 5] = sq;
    __syncthreads();
    float var = (r2[0] + r2[1] + r2[2] + r2[3]) * (1.f/128.f);
    out[row*DD + t] = d * rsqrtf(var + 1e-5f) * g[t] + b[t];
}

// ln1: harness input x -> g_xn (device global, direct)
__global__ void ln1_kernel(const float* __restrict__ x, const float* __restrict__ g,
                           const float* __restrict__ b) {
    ln128_body(x, g_xn, g, b);
}
// ln2: g_x1 (device global, direct) -> g_xn (device global, direct)
__global__ void ln2_kernel(const float* __restrict__ g, const float* __restrict__ b) {
    ln128_body(g_x1, g_xn, g, b);
}

// ---------------- QKV: 3 fused 128x128 row-GEMMs (reads g_xn directly) ----------------
__global__ void qkv_kernel(const float* __restrict__ Wq, const float* __restrict__ Wk,
                           const float* __restrict__ Wv) {
    int row = blockIdx.x, t = threadIdx.x;
    __shared__ float xs[DD];
    xs[t] = g_xn[row*DD + t];
    __syncthreads();
    float aq = 0.f, ak = 0.f, av = 0.f;
    #pragma unroll 4
    for (int kk = 0; kk < DD; kk++) {
        float xv = xs[kk];
        aq = fmaf(xv, Wq[kk*DD + t], aq);
        ak = fmaf(xv, Wk[kk*DD + t], ak);
        av = fmaf(xv, Wv[kk*DD + t], av);
    }
    g_q[row*DD + t] = aq;
    g_k[row*DD + t] = ak;
    g_v[row*DD + t] = av;
}

// ---------------- bias[b,i,j,h] = sum_p z[b,i,j,p] * Wb[p,h] ----------------
// one warp per (b,i,j). 8 warps / block.
__global__ void bias_kernel(const float* __restrict__ z, const float* __restrict__ Wb) {
    __shared__ float wbs[NH*DP];   // wbs[h*64+p] = Wb[p*8+h]
    int t = threadIdx.x;
    for (int i = t; i < NH*DP; i += 256) {
        int h = i >> 6, p = i & 63;
        wbs[i] = Wb[p*NH + h];
    }
    __syncthreads();
    int gw = (blockIdx.x * blockDim.x + t) >> 5;
    if (gw >= NPAIR) return;
    int lane = t & 31;
    const float* zp = z + (size_t)gw * DP;
    float z0 = zp[lane], z1 = zp[lane + 32];
    float acc[NH];
    #pragma unroll
    for (int h = 0; h < NH; h++)
        acc[h] = z0 * wbs[h*64 + lane] + z1 * wbs[h*64 + lane + 32];
    #pragma unroll
    for (int h = 0; h < NH; h++) {
        #pragma unroll
        for (int o = 16; o; o >>= 1) acc[h] += __shfl_down_sync(0xffffffffu, acc[h], o);
    }
    if (lane == 0) {
        float* bp = g_bias + (size_t)gw * NH;
        #pragma unroll
        for (int h = 0; h < NH; h++) bp[h] = acc[h];
    }
}

// ---------------- attention: one block per (b,i), all 8 heads ----------------
__global__ void attn_kernel() {
    int bi = blockIdx.x;            // b*L + i
    int b = bi / LL;
    int t = threadIdx.x;
    __shared__ float qs[DD];
    __shared__ float sc[NH*LL];     // 2560 floats
    __shared__ float part[DD];
    if (t < DD) qs[t] = g_q[bi*DD + t];
    __syncthreads();
    // phase 1: scores
    for (int idx = t; idx < NH*LL; idx += 256) {
        int h = idx / LL, j = idx - h*LL;
        const float* kp = g_k + ((size_t)(b*LL + j))*DD + h*DH;
        float acc = 0.f;
        #pragma unroll
        for (int d = 0; d < DH; d++) acc = fmaf(qs[h*DH + d], kp[d], acc);
        sc[h*LL + j] = acc * 0.25f + g_bias[((size_t)bi*LL + j)*NH + h];
    }
    __syncthreads();
    // phase 2: softmax, warp w handles head w
    int w = t >> 5, lane = t & 31;
    float m = -INFINITY;
    for (int j = lane; j < LL; j += 32) m = fmaxf(m, sc[w*LL + j]);
    m = warp_max(m);
    float s = 0.f;
    for (int j = lane; j < LL; j += 32) {
        float e = __expf(sc[w*LL + j] - m);
        sc[w*LL + j] = e;
        s += e;
    }
    s = warp_sum(s);
    float inv = 1.f / s;
    for (int j = lane; j < LL; j += 32) sc[w*LL + j] *= inv;
    __syncthreads();
    // phase 3: out[c] = sum_j probs[h,j] * v[b,j,c]   (c = h*16+d)
    int c = t & 127, half = t >> 7;
    int h = c >> 4;
    const float* vp = g_v + (size_t)b*LL*DD + c;
    float acc = 0.f;
    int jb = half * (LL/2), je = jb + LL/2;
    for (int j = jb; j < je; j++) acc = fmaf(sc[h*LL + j], vp[(size_t)j*DD], acc);
    if (half == 1) part[c] = acc;
    __syncthreads();
    if (half == 0) g_attn[bi*DD + c] = acc + part[c];
}

// ---------------- x1 = x + attn@Wo + bo ----------------
__global__ void proj_kernel(const float* __restrict__ x, const float* __restrict__ Wo,
                            const float* __restrict__ bo) {
    int row = blockIdx.x, t = threadIdx.x;
    __shared__ float as[DD];
    as[t] = g_attn[row*DD + t];
    __syncthreads();
    float acc = 0.f;
    #pragma unroll 4
    for (int kk = 0; kk < DD; kk++) acc = fmaf(as[kk], Wo[kk*DD + t], acc);
    g_x1[row*DD + t] = x[row*DD + t] + acc + bo[t];
}

// ---------------- ffn1: h = gelu(xn2 @ W1 + b1), 512 cols ----------------
__global__ void ffn1_kernel(const float* __restrict__ W1, const float* __restrict__ b1) {
    int row = blockIdx.x, t = threadIdx.x;
    __shared__ float xs[DD];
    if (t < DD) xs[t] = g_xn[row*DD + t];
    __syncthreads();
    #pragma unroll
    for (int cc = 0; cc < 2; cc++) {
        int c = t + cc*256;
        float acc = b1[c];
        #pragma unroll 4
        for (int kk = 0; kk < DD; kk++) acc = fmaf(xs[kk], W1[kk*512 + c], acc);
        float gv = 0.5f * acc * (1.f + erff(acc * 0.70710678118654752f));
        g_h[(size_t)row*512 + c] = gv;
    }
}

// ---------------- ffn2: x2 = x1 + h @ W2 + b2 -> out_x ----------------
__global__ void ffn2_kernel(const float* __restrict__ W2, const float* __restrict__ b2,
                            float* __restrict__ out_x) {
    int row = blockIdx.x, t = threadIdx.x;
    __shared__ float hs[512];
    #pragma unroll
    for (int i = 0; i < 4; i++) hs[t + i*128] = g_h[(size_t)row*512 + t + i*128];
    __syncthreads();
    float acc = 0.f;
    #pragma unroll 4
    for (int kk = 0; kk < 512; kk++) acc = fmaf(hs[kk], W2[kk*DD + t], acc);
    out_x[row*DD + t] = g_x1[row*DD + t] + acc + b2[t];
}

// ---------------- p1/p2 projections (reads final x from d_out) ----------------
__global__ void pproj_kernel(const float* __restrict__ xf,
                             const float* __restrict__ Wp1, const float* __restrict__ bp1,
                             const float* __restrict__ Wp2, const float* __restrict__ bp2) {
    int row = blockIdx.x, t = threadIdx.x;   // 64 threads
    __shared__ float xs[DD];
    xs[t] = xf[row*DD + t];
    xs[t + 64] = xf[row*DD + t + 64];
    __syncthreads();
    if (t < DO) {
        float acc = bp1[t];
        #pragma unroll 4
        for (int kk = 0; kk < DD; kk++) acc = fmaf(xs[kk], Wp1[kk*DO + t], acc);
        g_p1[row*DO + t] = acc;
    } else {
        int c = t - DO;
        float acc = bp2[c];
        #pragma unroll 4
        for (int kk = 0; kk < DD; kk++) acc = fmaf(xs[kk], Wp2[kk*DO + c], acc);
        g_p2[row*DO + c] = acc;
    }
}

// ---------------- A[row, d, p] = sum_c p1[row,c] * Wz[(c*32+d)*64+p] ----------------
__global__ void a_kernel(const float* __restrict__ Wz) {
    int r0 = blockIdx.x * 8;
    int t = threadIdx.x;
    __shared__ float p1s[8][DO];
    { int r = t >> 5, c = t & 31; p1s[r][c] = g_p1[(r0 + r)*DO + c]; }
    __syncthreads();
    for (int dp = t; dp < DO*DP; dp += 256) {
        float acc[8] = {0,0,0,0,0,0,0,0};
        #pragma unroll 4
        for (int c = 0; c < DO; c++) {
            float wv = Wz[(size_t)c*(DO*DP) + dp];
            #pragma unroll
            for (int r = 0; r < 8; r++) acc[r] = fmaf(p1s[r][c], wv, acc[r]);
        }
        #pragma unroll
        for (int r = 0; r < 8; r++) g_A[(size_t)(r0 + r)*(DO*DP) + dp] = acc[r];
    }
}

// ---------------- final: z_out = LN(z + A(i)·p2(j) + bz) ----------------
__global__ void pair_final_kernel(const float* __restrict__ z, const float* __restrict__ bz,
                                  const float* __restrict__ g, const float* __restrict__ be,
                                  float* __restrict__ zout) {
    int bi = blockIdx.x;
    int b = bi / LL;
    int t = threadIdx.x, w = t >> 5, lane = t & 31;
    __shared__ float2 As2[DO*DP/2];   // [d][p/2] 1024 float2
    const float2* Ag = (const float2*)(g_A + (size_t)bi*(DO*DP));
    for (int idx = t; idx < DO*DP/2; idx += 256) As2[idx] = Ag[idx];
    __syncthreads();
    float bz0 = bz[2*lane], bz1 = bz[2*lane + 1];
    float g0 = g[2*lane],  g1 = g[2*lane + 1];
    float e0 = be[2*lane], e1 = be[2*lane + 1];
    size_t zbase = (size_t)bi * LL * DP;
    const float* p2b = g_p2 + (size_t)b * LL * DO;
    for (int j = w; j < LL; j += 8) {
        float p2v = p2b[j*DO + lane];
        float acc0 = 0.f, acc1 = 0.f;
        #pragma unroll
        for (int d = 0; d < DO; d++) {
            float s = __shfl_sync(0xffffffffu, p2v, d);
            float2 av = As2[d*32 + lane];
            acc0 = fmaf(s, av.x, acc0);
            acc1 = fmaf(s, av.y, acc1);
        }
        float2 zv = *(const float2*)(z + zbase + (size_t)j*DP + 2*lane);
        float v0 = zv.x + acc0 + bz0;
        float v1 = zv.y + acc1 + bz1;
        float mu = warp_sum(v0 + v1) * (1.f/64.f);
        float d0 = v0 - mu, d1 = v1 - mu;
        float var = warp_sum(d0*d0 + d1*d1) * (1.f/64.f);
        float rs = rsqrtf(var + 1e-5f);
        float2 o;
        o.x = d0 * rs * g0 + e0;
        o.y = d1 * rs * g1 + e1;
        *(float2*)(zout + zbase + (size_t)j*DP + 2*lane) = o;
    }
}

extern "C" void kernel_launch(void* const* d_in, const int* in_sizes, int n_in,
                              void* d_out, int out_size) {
    const float* x      = (const float*)d_in[0];
    const float* z      = (const float*)d_in[1];
    const float* Wq     = (const float*)d_in[2];
    const float* Wk     = (const float*)d_in[3];
    const float* Wv     = (const float*)d_in[4];
    const float* Wb     = (const float*)d_in[5];
    const float* Wo     = (const float*)d_in[6];
    const float* bo     = (const float*)d_in[7];
    const float* ln1_g  = (const float*)d_in[8];
    const float* ln1_b  = (const float*)d_in[9];
    const float* W1     = (const float*)d_in[10];
    const float* b1     = (const float*)d_in[11];
    const float* W2     = (const float*)d_in[12];
    const float* b2     = (const float*)d_in[13];
    const float* ln2_g  = (const float*)d_in[14];
    const float* ln2_b  = (const float*)d_in[15];
    const float* Wp1    = (const float*)d_in[16];
    const float* bp1    = (const float*)d_in[17];
    const float* Wp2    = (const float*)d_in[18];
    const float* bp2    = (const float*)d_in[19];
    const float* Wz     = (const float*)d_in[20];
    const float* bz     = (const float*)d_in[21];
    const float* lnp_g  = (const float*)d_in[22];
    const float* lnp_b  = (const float*)d_in[23];

    float* out_x = (float*)d_out;                       // [B,L,D]
    float* out_z = (float*)d_out + (size_t)NROW*DD;     // [B,L,L,DP]

    ln1_kernel<<<NROW, 128>>>(x, ln1_g, ln1_b);
    qkv_kernel<<<NROW, 128>>>(Wq, Wk, Wv);
    bias_kernel<<<NPAIR/8, 256>>>(z, Wb);
    attn_kernel<<<NROW, 256>>>();
    proj_kernel<<<NROW, 128>>>(x, Wo, bo);
    ln2_kernel<<<NROW, 128>>>(ln2_g, ln2_b);
    ffn1_kernel<<<NROW, 256>>>(W1, b1);
    ffn2_kernel<<<NROW, 128>>>(W2, b2, out_x);
    pproj_kernel<<<NROW, 64>>>(out_x, Wp1, bp1, Wp2, bp2);
    a_kernel<<<NROW/8, 256>>>(Wz);
    pair_final_kernel<<<NROW, 256>>>(z, bz, lnp_g, lnp_b, out_z);
}

// round 4
// speedup vs baseline: 1.2330x; 1.2330x over previous
#include <cuda_runtime.h>
#include <math.h>

#define BB 2
#define LL 320
#define DD 128
#define DP 64
#define NH 8
#define DH 16
#define DO 32
#define NROW (BB*LL)          // 640
#define NPAIR (BB*LL*LL)      // 204800
#define SCP 321               // padded score row (bank-conflict-free across heads)

// ---------------- scratch (allocation-free, device-side references ONLY) ----------------
__device__ float g_xn[NROW*DD];
__device__ float g_q [NROW*DD];
__device__ float g_k [NROW*DD];
__device__ float g_v [NROW*DD];
__device__ float g_bias[NPAIR*NH];     // [b,i,j,h]
__device__ float g_attn[NROW*DD];
__device__ float g_x1[NROW*DD];
__device__ float g_h [NROW*4*DD];
__device__ float g_p1[NROW*DO];
__device__ float g_p2[NROW*DO];
__device__ float g_A [NROW*DO*DP];     // [row, d, p]

__device__ __forceinline__ float warp_sum(float v) {
    #pragma unroll
    for (int o = 16; o; o >>= 1) v += __shfl_xor_sync(0xffffffffu, v, o);
    return v;
}
__device__ __forceinline__ float warp_max(float v) {
    #pragma unroll
    for (int o = 16; o; o >>= 1) v = fmaxf(v, __shfl_xor_sync(0xffffffffu, v, o));
    return v;
}

// ---------------- fused ln1 + QKV: one row per block, 128 threads ----------------
__global__ void ln1_qkv_kernel(const float* __restrict__ x,
                               const float* __restrict__ lg, const float* __restrict__ lb,
                               const float* __restrict__ Wq, const float* __restrict__ Wk,
                               const float* __restrict__ Wv) {
    int row = blockIdx.x, t = threadIdx.x;
    __shared__ float xs[DD];
    __shared__ float r1[4], r2[4];
    float v = x[row*DD + t];
    float s = warp_sum(v);
    if ((t & 31) == 0) r1[t >> 5] = s;
    __syncthreads();
    float mu = (r1[0] + r1[1] + r1[2] + r1[3]) * (1.f/128.f);
    float d = v - mu;
    float sq = warp_sum(d*d);
    if ((t & 31) == 0) r2[t >> 5] = sq;
    __syncthreads();
    float var = (r2[0] + r2[1] + r2[2] + r2[3]) * (1.f/128.f);
    xs[t] = d * rsqrtf(var + 1e-5f) * lg[t] + lb[t];
    __syncthreads();
    float aq = 0.f, ak = 0.f, av = 0.f;
    #pragma unroll 4
    for (int kk = 0; kk < DD; kk++) {
        float xv = xs[kk];
        aq = fmaf(xv, Wq[kk*DD + t], aq);
        ak = fmaf(xv, Wk[kk*DD + t], ak);
        av = fmaf(xv, Wv[kk*DD + t], av);
    }
    g_q[row*DD + t] = aq;
    g_k[row*DD + t] = ak;
    g_v[row*DD + t] = av;
}

// ---------------- bias[b,i,j,h] = sum_p z[b,i,j,p] * Wb[p,h] ----------------
__global__ void bias_kernel(const float* __restrict__ z, const float* __restrict__ Wb) {
    __shared__ float wbs[NH*DP];   // wbs[h*64+p] = Wb[p*8+h]
    int t = threadIdx.x;
    for (int i = t; i < NH*DP; i += 256) {
        int h = i >> 6, p = i & 63;
        wbs[i] = Wb[p*NH + h];
    }
    __syncthreads();
    int gw = (blockIdx.x * blockDim.x + t) >> 5;
    if (gw >= NPAIR) return;
    int lane = t & 31;
    const float* zp = z + (size_t)gw * DP;
    float z0 = zp[lane], z1 = zp[lane + 32];
    float acc[NH];
    #pragma unroll
    for (int h = 0; h < NH; h++)
        acc[h] = z0 * wbs[h*64 + lane] + z1 * wbs[h*64 + lane + 32];
    #pragma unroll
    for (int h = 0; h < NH; h++) {
        #pragma unroll
        for (int o = 16; o; o >>= 1) acc[h] += __shfl_down_sync(0xffffffffu, acc[h], o);
    }
    if (lane == 0) {
        float* bp = g_bias + (size_t)gw * NH;
        #pragma unroll
        for (int h = 0; h < NH; h++) bp[h] = acc[h];
    }
}

// ---------------- attention: one block per (b,i), 8 heads, V tiled via SMEM ----------------
__global__ void attn_kernel() {
    int bi = blockIdx.x;            // b*L + i
    int b = bi / LL;
    int t = threadIdx.x;            // 256
    __shared__ float qs[DD];
    __shared__ float sc[NH*SCP];
    __shared__ float vs[32*DD];     // 16 KB V tile
    __shared__ float part[DD];
    if (t < DD) qs[t] = g_q[bi*DD + t];
    __syncthreads();
    // phase 1: scores (16B-vectorized K reads)
    for (int idx = t; idx < NH*LL; idx += 256) {
        int h = idx / LL, j = idx - h*LL;
        const float4* kp = (const float4*)(g_k + ((size_t)(b*LL + j))*DD + h*DH);
        const float4* qp = (const float4*)(qs + h*DH);
        float acc = 0.f;
        #pragma unroll
        for (int d4 = 0; d4 < 4; d4++) {
            float4 kv = kp[d4], qv = qp[d4];
            acc = fmaf(qv.x, kv.x, acc);
            acc = fmaf(qv.y, kv.y, acc);
            acc = fmaf(qv.z, kv.z, acc);
            acc = fmaf(qv.w, kv.w, acc);
        }
        sc[h*SCP + j] = acc * 0.25f + g_bias[((size_t)bi*LL + j)*NH + h];
    }
    __syncthreads();
    // phase 2: softmax, warp w = head w
    int w = t >> 5, lane = t & 31;
    float m = -INFINITY;
    for (int j = lane; j < LL; j += 32) m = fmaxf(m, sc[w*SCP + j]);
    m = warp_max(m);
    float s = 0.f;
    for (int j = lane; j < LL; j += 32) {
        float e = __expf(sc[w*SCP + j] - m);
        sc[w*SCP + j] = e;
        s += e;
    }
    s = warp_sum(s);
    float inv = 1.f / s;
    for (int j = lane; j < LL; j += 32) sc[w*SCP + j] *= inv;
    __syncthreads();
    // phase 3: out[c] = sum_j probs[h,j] * v[b,j,c], V staged via SMEM tiles of 32 rows
    int c = t & 127, half = t >> 7;
    int h = c >> 4;
    float acc = 0.f;
    int jb = half * 16;
    for (int j0 = 0; j0 < LL; j0 += 32) {
        const float4* vsrc = (const float4*)(g_v + ((size_t)(b*LL + j0))*DD);
        float4* vdst = (float4*)vs;
        #pragma unroll
        for (int i = 0; i < 4; i++) vdst[t + i*256] = vsrc[t + i*256];
        __syncthreads();
        #pragma unroll
        for (int jj = 0; jj < 16; jj++)
            acc = fmaf(sc[h*SCP + j0 + jb + jj], vs[(jb + jj)*DD + c], acc);
        __syncthreads();
    }
    if (half == 1) part[c] = acc;
    __syncthreads();
    if (half == 0) g_attn[bi*DD + c] = acc + part[c];
}

// ---------------- fused proj + ln2: x1 = x + attn@Wo + bo; xn = LN(x1) ----------------
__global__ void proj_ln2_kernel(const float* __restrict__ x, const float* __restrict__ Wo,
                                const float* __restrict__ bo,
                                const float* __restrict__ lg, const float* __restrict__ lb) {
    int row = blockIdx.x, t = threadIdx.x;
    __shared__ float as[DD];
    __shared__ float r1[4], r2[4];
    as[t] = g_attn[row*DD + t];
    __syncthreads();
    float acc = 0.f;
    #pragma unroll 4
    for (int kk = 0; kk < DD; kk++) acc = fmaf(as[kk], Wo[kk*DD + t], acc);
    float v = x[row*DD + t] + acc + bo[t];
    g_x1[row*DD + t] = v;
    float s = warp_sum(v);
    if ((t & 31) == 0) r1[t >> 5] = s;
    __syncthreads();
    float mu = (r1[0] + r1[1] + r1[2] + r1[3]) * (1.f/128.f);
    float d = v - mu;
    float sq = warp_sum(d*d);
    if ((t & 31) == 0) r2[t >> 5] = sq;
    __syncthreads();
    float var = (r2[0] + r2[1] + r2[2] + r2[3]) * (1.f/128.f);
    g_xn[row*DD + t] = d * rsqrtf(var + 1e-5f) * lg[t] + lb[t];
}

// ---------------- ffn1: h = gelu(xn2 @ W1 + b1), 512 cols ----------------
__global__ void ffn1_kernel(const float* __restrict__ W1, const float* __restrict__ b1) {
    int row = blockIdx.x, t = threadIdx.x;
    __shared__ float xs[DD];
    if (t < DD) xs[t] = g_xn[row*DD + t];
    __syncthreads();
    #pragma unroll
    for (int cc = 0; cc < 2; cc++) {
        int c = t + cc*256;
        float acc = b1[c];
        #pragma unroll 4
        for (int kk = 0; kk < DD; kk++) acc = fmaf(xs[kk], W1[kk*512 + c], acc);
        float gv = 0.5f * acc * (1.f + erff(acc * 0.70710678118654752f));
        g_h[(size_t)row*512 + c] = gv;
    }
}

// ---------------- fused ffn2 + pproj: x2 -> out_x, then p1/p2 ----------------
__global__ void ffn2_pproj_kernel(const float* __restrict__ W2, const float* __restrict__ b2,
                                  float* __restrict__ out_x,
                                  const float* __restrict__ Wp1, const float* __restrict__ bp1,
                                  const float* __restrict__ Wp2, const float* __restrict__ bp2) {
    int row = blockIdx.x, t = threadIdx.x;   // 128 threads
    __shared__ float hs[512];
    __shared__ float xs[DD];
    #pragma unroll
    for (int i = 0; i < 4; i++) hs[t + i*128] = g_h[(size_t)row*512 + t + i*128];
    __syncthreads();
    float acc = 0.f;
    #pragma unroll 4
    for (int kk = 0; kk < 512; kk++) acc = fmaf(hs[kk], W2[kk*DD + t], acc);
    float xv = g_x1[row*DD + t] + acc + b2[t];
    out_x[row*DD + t] = xv;
    xs[t] = xv;
    __syncthreads();
    if (t < DO) {
        float a = bp1[t];
        #pragma unroll 4
        for (int kk = 0; kk < DD; kk++) a = fmaf(xs[kk], Wp1[kk*DO + t], a);
        g_p1[row*DO + t] = a;
    } else if (t < 2*DO) {
        int c = t - DO;
        float a = bp2[c];
        #pragma unroll 4
        for (int kk = 0; kk < DD; kk++) a = fmaf(xs[kk], Wp2[kk*DO + c], a);
        g_p2[row*DO + c] = a;
    }
}

// ---------------- A[row, d, p] = sum_c p1[row,c] * Wz[(c*32+d)*64+p] ----------------
__global__ void a_kernel(const float* __restrict__ Wz) {
    int r0 = blockIdx.x * 8;
    int t = threadIdx.x;
    __shared__ float p1s[8][DO];
    { int r = t >> 5, c = t & 31; p1s[r][c] = g_p1[(r0 + r)*DO + c]; }
    __syncthreads();
    for (int dp = t; dp < DO*DP; dp += 256) {
        float acc[8] = {0,0,0,0,0,0,0,0};
        #pragma unroll 4
        for (int c = 0; c < DO; c++) {
            float wv = Wz[(size_t)c*(DO*DP) + dp];
            #pragma unroll
            for (int r = 0; r < 8; r++) acc[r] = fmaf(p1s[r][c], wv, acc[r]);
        }
        #pragma unroll
        for (int r = 0; r < 8; r++) g_A[(size_t)(r0 + r)*(DO*DP) + dp] = acc[r];
    }
}

// ---------------- final: z_out = LN(z + A(i)·p2(j) + bz), A held in registers ----------------
__global__ void __launch_bounds__(256, 2)
pair_final_kernel(const float* __restrict__ z, const float* __restrict__ bz,
                  const float* __restrict__ g, const float* __restrict__ be,
                  float* __restrict__ zout) {
    int bi = blockIdx.x;
    int b = bi / LL;
    int t = threadIdx.x, w = t >> 5, lane = t & 31;
    // each warp loads the whole A(i) tile into registers: a[d] = A[d][2*lane .. 2*lane+1]
    const float2* Ag = (const float2*)(g_A + (size_t)bi*(DO*DP));
    float2 a[DO];
    #pragma unroll
    for (int d = 0; d < DO; d++) a[d] = Ag[d*32 + lane];
    float bz0 = bz[2*lane], bz1 = bz[2*lane + 1];
    float g0 = g[2*lane],  g1 = g[2*lane + 1];
    float e0 = be[2*lane], e1 = be[2*lane + 1];
    size_t zbase = (size_t)bi * LL * DP;
    const float* p2b = g_p2 + (size_t)b * LL * DO;
    for (int j = w; j < LL; j += 8) {
        float p2v = p2b[j*DO + lane];
        float acc0 = 0.f, acc1 = 0.f;
        #pragma unroll
        for (int d = 0; d < DO; d++) {
            float s = __shfl_sync(0xffffffffu, p2v, d);
            acc0 = fmaf(s, a[d].x, acc0);
            acc1 = fmaf(s, a[d].y, acc1);
        }
        float2 zv = *(const float2*)(z + zbase + (size_t)j*DP + 2*lane);
        float v0 = zv.x + acc0 + bz0;
        float v1 = zv.y + acc1 + bz1;
        float mu = warp_sum(v0 + v1) * (1.f/64.f);
        float d0 = v0 - mu, d1 = v1 - mu;
        float var = warp_sum(d0*d0 + d1*d1) * (1.f/64.f);
        float rs = rsqrtf(var + 1e-5f);
        float2 o;
        o.x = d0 * rs * g0 + e0;
        o.y = d1 * rs * g1 + e1;
        *(float2*)(zout + zbase + (size_t)j*DP + 2*lane) = o;
    }
}

extern "C" void kernel_launch(void* const* d_in, const int* in_sizes, int n_in,
                              void* d_out, int out_size) {
    const float* x      = (const float*)d_in[0];
    const float* z      = (const float*)d_in[1];
    const float* Wq     = (const float*)d_in[2];
    const float* Wk     = (const float*)d_in[3];
    const float* Wv     = (const float*)d_in[4];
    const float* Wb     = (const float*)d_in[5];
    const float* Wo     = (const float*)d_in[6];
    const float* bo     = (const float*)d_in[7];
    const float* ln1_g  = (const float*)d_in[8];
    const float* ln1_b  = (const float*)d_in[9];
    const float* W1     = (const float*)d_in[10];
    const float* b1     = (const float*)d_in[11];
    const float* W2     = (const float*)d_in[12];
    const float* b2     = (const float*)d_in[13];
    const float* ln2_g  = (const float*)d_in[14];
    const float* ln2_b  = (const float*)d_in[15];
    const float* Wp1    = (const float*)d_in[16];
    const float* bp1    = (const float*)d_in[17];
    const float* Wp2    = (const float*)d_in[18];
    const float* bp2    = (const float*)d_in[19];
    const float* Wz     = (const float*)d_in[20];
    const float* bz     = (const float*)d_in[21];
    const float* lnp_g  = (const float*)d_in[22];
    const float* lnp_b  = (const float*)d_in[23];

    float* out_x = (float*)d_out;                       // [B,L,D]
    float* out_z = (float*)d_out + (size_t)NROW*DD;     // [B,L,L,DP]

    ln1_qkv_kernel<<<NROW, 128>>>(x, ln1_g, ln1_b, Wq, Wk, Wv);
    bias_kernel<<<NPAIR/8, 256>>>(z, Wb);
    attn_kernel<<<NROW, 256>>>();
    proj_ln2_kernel<<<NROW, 128>>>(x, Wo, bo, ln2_g, ln2_b);
    ffn1_kernel<<<NROW, 256>>>(W1, b1);
    ffn2_pproj_kernel<<<NROW, 128>>>(W2, b2, out_x, Wp1, bp1, Wp2, bp2);
    a_kernel<<<NROW/8, 256>>>(Wz);
    pair_final_kernel<<<NROW, 256>>>(z, bz, lnp_g, lnp_b, out_z);
}

// round 6
// speedup vs baseline: 1.6608x; 1.3470x over previous
#include <cuda_runtime.h>
#include <math.h>

#define BB 2
#define LL 320
#define DD 128
#define DP 64
#define NH 8
#define DH 16
#define DO 32
#define NROW (BB*LL)          // 640
#define NPAIR (BB*LL*LL)      // 204800
#define SCP 321               // padded score row

// ---------------- scratch (allocation-free, device-side references ONLY) ----------------
__device__ float g_xn[NROW*DD];
__device__ float g_q [NROW*DD];
__device__ float g_k [NROW*DD];
__device__ float g_v [NROW*DD];
__device__ float g_bias[NPAIR*NH];     // [b,i,j,h]
__device__ float g_attn[NROW*DD];
__device__ float g_x1[NROW*DD];
__device__ float g_h [NROW*4*DD];
__device__ float g_p1[NROW*DO];
__device__ float g_p2[NROW*DO];
__device__ float g_A [NROW*DO*DP];     // [row, d, p]

__device__ __forceinline__ float warp_sum(float v) {
    #pragma unroll
    for (int o = 16; o; o >>= 1) v += __shfl_xor_sync(0xffffffffu, v, o);
    return v;
}
__device__ __forceinline__ float warp_max(float v) {
    #pragma unroll
    for (int o = 16; o; o >>= 1) v = fmaxf(v, __shfl_xor_sync(0xffffffffu, v, o));
    return v;
}

// ---------------- fused ln1 + QKV ----------------
__global__ void ln1_qkv_kernel(const float* __restrict__ x,
                               const float* __restrict__ lg, const float* __restrict__ lb,
                               const float* __restrict__ Wq, const float* __restrict__ Wk,
                               const float* __restrict__ Wv) {
    int row = blockIdx.x, t = threadIdx.x;
    __shared__ float xs[DD];
    __shared__ float r1[4], r2[4];
    float v = x[row*DD + t];
    float s = warp_sum(v);
    if ((t & 31) == 0) r1[t >> 5] = s;
    __syncthreads();
    float mu = (r1[0] + r1[1] + r1[2] + r1[3]) * (1.f/128.f);
    float d = v - mu;
    float sq = warp_sum(d*d);
    if ((t & 31) == 0) r2[t >> 5] = sq;
    __syncthreads();
    float var = (r2[0] + r2[1] + r2[2] + r2[3]) * (1.f/128.f);
    xs[t] = d * rsqrtf(var + 1e-5f) * lg[t] + lb[t];
    __syncthreads();
    float aq0=0.f, aq1=0.f, ak0=0.f, ak1=0.f, av0=0.f, av1=0.f;
    #pragma unroll 8
    for (int kk = 0; kk < DD; kk += 2) {
        float x0 = xs[kk], x1 = xs[kk+1];
        aq0 = fmaf(x0, Wq[kk*DD + t], aq0);
        ak0 = fmaf(x0, Wk[kk*DD + t], ak0);
        av0 = fmaf(x0, Wv[kk*DD + t], av0);
        aq1 = fmaf(x1, Wq[(kk+1)*DD + t], aq1);
        ak1 = fmaf(x1, Wk[(kk+1)*DD + t], ak1);
        av1 = fmaf(x1, Wv[(kk+1)*DD + t], av1);
    }
    g_q[row*DD + t] = aq0 + aq1;
    g_k[row*DD + t] = ak0 + ak1;
    g_v[row*DD + t] = av0 + av1;
}

// ---------------- bias: smem-tiled, one (pair,h) output per thread ----------------
__global__ void bias_kernel(const float* __restrict__ z, const float* __restrict__ Wb) {
    __shared__ __align__(16) float zs[32][68];   // 32 pairs x 64 (+4 pad)
    __shared__ float wbs[DP][NH];                // [p][h]
    int t = threadIdx.x;                         // 256
    // Wb has DP*NH = 512 entries; 256 threads -> 2 strided passes
    wbs[t >> 3][t & 7] = Wb[t];
    { int i2 = t + 256; wbs[i2 >> 3][i2 & 7] = Wb[i2]; }
    size_t base = (size_t)blockIdx.x * 32 * DP;
    const float4* zsrc = (const float4*)(z + base);
    #pragma unroll
    for (int i = 0; i < 2; i++) {
        int idx = t + i*256;          // 0..511 float4s
        int pair = idx >> 4, c4 = idx & 15;
        *((float4*)&zs[pair][c4*4]) = zsrc[idx];
    }
    __syncthreads();
    int pair = t >> 3, h = t & 7;
    float a0 = 0.f, a1 = 0.f;
    #pragma unroll
    for (int p = 0; p < DP; p += 2) {
        a0 = fmaf(zs[pair][p],   wbs[p][h],   a0);
        a1 = fmaf(zs[pair][p+1], wbs[p+1][h], a1);
    }
    g_bias[(size_t)blockIdx.x * 256 + t] = a0 + a1;   // coalesced [pair][h]
}

// ---------------- attention: one block per (b,i), V tiled via SMEM ----------------
__global__ void attn_kernel() {
    int bi = blockIdx.x;
    int b = bi / LL;
    int t = threadIdx.x;            // 256
    __shared__ float qs[DD];
    __shared__ float sc[NH*SCP];
    __shared__ float vs[32*DD];
    __shared__ float part[DD];
    if (t < DD) qs[t] = g_q[bi*DD + t];
    __syncthreads();
    for (int idx = t; idx < NH*LL; idx += 256) {
        int h = idx / LL, j = idx - h*LL;
        const float4* kp = (const float4*)(g_k + ((size_t)(b*LL + j))*DD + h*DH);
        const float4* qp = (const float4*)(qs + h*DH);
        float acc = 0.f;
        #pragma unroll
        for (int d4 = 0; d4 < 4; d4++) {
            float4 kv = kp[d4], qv = qp[d4];
            acc = fmaf(qv.x, kv.x, acc);
            acc = fmaf(qv.y, kv.y, acc);
            acc = fmaf(qv.z, kv.z, acc);
            acc = fmaf(qv.w, kv.w, acc);
        }
        sc[h*SCP + j] = acc * 0.25f + g_bias[((size_t)bi*LL + j)*NH + h];
    }
    __syncthreads();
    int w = t >> 5, lane = t & 31;
    float m = -INFINITY;
    for (int j = lane; j < LL; j += 32) m = fmaxf(m, sc[w*SCP + j]);
    m = warp_max(m);
    float s = 0.f;
    for (int j = lane; j < LL; j += 32) {
        float e = __expf(sc[w*SCP + j] - m);
        sc[w*SCP + j] = e;
        s += e;
    }
    s = warp_sum(s);
    float inv = 1.f / s;
    for (int j = lane; j < LL; j += 32) sc[w*SCP + j] *= inv;
    __syncthreads();
    int c = t & 127, half = t >> 7;
    int h = c >> 4;
    float acc = 0.f;
    int jb = half * 16;
    for (int j0 = 0; j0 < LL; j0 += 32) {
        const float4* vsrc = (const float4*)(g_v + ((size_t)(b*LL + j0))*DD);
        float4* vdst = (float4*)vs;
        #pragma unroll
        for (int i = 0; i < 4; i++) vdst[t + i*256] = vsrc[t + i*256];
        __syncthreads();
        #pragma unroll
        for (int jj = 0; jj < 16; jj++)
            acc = fmaf(sc[h*SCP + j0 + jb + jj], vs[(jb + jj)*DD + c], acc);
        __syncthreads();
    }
    if (half == 1) part[c] = acc;
    __syncthreads();
    if (half == 0) g_attn[bi*DD + c] = acc + part[c];
}

// ---------------- fused proj + ln2 ----------------
__global__ void proj_ln2_kernel(const float* __restrict__ x, const float* __restrict__ Wo,
                                const float* __restrict__ bo,
                                const float* __restrict__ lg, const float* __restrict__ lb) {
    int row = blockIdx.x, t = threadIdx.x;
    __shared__ float as[DD];
    __shared__ float r1[4], r2[4];
    as[t] = g_attn[row*DD + t];
    __syncthreads();
    float a0=0.f, a1=0.f, a2=0.f, a3=0.f;
    #pragma unroll
    for (int kk = 0; kk < DD; kk += 4) {
        a0 = fmaf(as[kk],   Wo[kk*DD + t],     a0);
        a1 = fmaf(as[kk+1], Wo[(kk+1)*DD + t], a1);
        a2 = fmaf(as[kk+2], Wo[(kk+2)*DD + t], a2);
        a3 = fmaf(as[kk+3], Wo[(kk+3)*DD + t], a3);
    }
    float v = x[row*DD + t] + (a0+a1) + (a2+a3) + bo[t];
    g_x1[row*DD + t] = v;
    float s = warp_sum(v);
    if ((t & 31) == 0) r1[t >> 5] = s;
    __syncthreads();
    float mu = (r1[0] + r1[1] + r1[2] + r1[3]) * (1.f/128.f);
    float d = v - mu;
    float sq = warp_sum(d*d);
    if ((t & 31) == 0) r2[t >> 5] = sq;
    __syncthreads();
    float var = (r2[0] + r2[1] + r2[2] + r2[3]) * (1.f/128.f);
    g_xn[row*DD + t] = d * rsqrtf(var + 1e-5f) * lg[t] + lb[t];
}

// ---------------- ffn1 ----------------
__global__ void ffn1_kernel(const float* __restrict__ W1, const float* __restrict__ b1) {
    int row = blockIdx.x, t = threadIdx.x;   // 256
    __shared__ float xs[DD];
    if (t < DD) xs[t] = g_xn[row*DD + t];
    __syncthreads();
    int c0 = t, c1 = t + 256;
    float a00=0.f, a01=0.f, a10=0.f, a11=0.f;
    #pragma unroll 8
    for (int kk = 0; kk < DD; kk += 2) {
        float x0 = xs[kk], x1 = xs[kk+1];
        a00 = fmaf(x0, W1[kk*512 + c0],     a00);
        a10 = fmaf(x0, W1[kk*512 + c1],     a10);
        a01 = fmaf(x1, W1[(kk+1)*512 + c0], a01);
        a11 = fmaf(x1, W1[(kk+1)*512 + c1], a11);
    }
    float v0 = a00 + a01 + b1[c0];
    float v1 = a10 + a11 + b1[c1];
    g_h[(size_t)row*512 + c0] = 0.5f * v0 * (1.f + erff(v0 * 0.70710678118654752f));
    g_h[(size_t)row*512 + c1] = 0.5f * v1 * (1.f + erff(v1 * 0.70710678118654752f));
}

// ---------------- fused ffn2 + pproj ----------------
__global__ void ffn2_pproj_kernel(const float* __restrict__ W2, const float* __restrict__ b2,
                                  float* __restrict__ out_x,
                                  const float* __restrict__ Wp1, const float* __restrict__ bp1,
                                  const float* __restrict__ Wp2, const float* __restrict__ bp2) {
    int row = blockIdx.x, t = threadIdx.x;   // 128
    __shared__ float hs[512];
    __shared__ float xs[DD];
    #pragma unroll
    for (int i = 0; i < 4; i++) hs[t + i*128] = g_h[(size_t)row*512 + t + i*128];
    __syncthreads();
    float a0=0.f, a1=0.f, a2=0.f, a3=0.f;
    #pragma unroll 4
    for (int kk = 0; kk < 512; kk += 4) {
        a0 = fmaf(hs[kk],   W2[kk*DD + t],     a0);
        a1 = fmaf(hs[kk+1], W2[(kk+1)*DD + t], a1);
        a2 = fmaf(hs[kk+2], W2[(kk+2)*DD + t], a2);
        a3 = fmaf(hs[kk+3], W2[(kk+3)*DD + t], a3);
    }
    float xv = g_x1[row*DD + t] + (a0+a1) + (a2+a3) + b2[t];
    out_x[row*DD + t] = xv;
    xs[t] = xv;
    __syncthreads();
    if (t < DO) {
        float b0=0.f, b1v=0.f;
        #pragma unroll 8
        for (int kk = 0; kk < DD; kk += 2) {
            b0  = fmaf(xs[kk],   Wp1[kk*DO + t],     b0);
            b1v = fmaf(xs[kk+1], Wp1[(kk+1)*DO + t], b1v);
        }
        g_p1[row*DO + t] = b0 + b1v + bp1[t];
    } else if (t < 2*DO) {
        int c = t - DO;
        float b0=0.f, b1v=0.f;
        #pragma unroll 8
        for (int kk = 0; kk < DD; kk += 2) {
            b0  = fmaf(xs[kk],   Wp2[kk*DO + c],     b0);
            b1v = fmaf(xs[kk+1], Wp2[(kk+1)*DO + c], b1v);
        }
        g_p2[row*DO + c] = b0 + b1v + bp2[c];
    }
}

// ---------------- A[row, d, p] = sum_c p1[row,c] * Wz[(c*32+d)*64+p] ----------------
__global__ void a_kernel(const float* __restrict__ Wz) {
    int r0 = blockIdx.x * 4;
    int t = threadIdx.x;              // 256
    __shared__ float p1s[4][DO];
    if (t < 128) { int r = t >> 5, c = t & 31; p1s[r][c] = g_p1[(r0 + r)*DO + c]; }
    __syncthreads();
    for (int dp = t; dp < DO*DP; dp += 256) {
        float acc[4] = {0,0,0,0};
        #pragma unroll 8
        for (int c = 0; c < DO; c++) {
            float wv = Wz[(size_t)c*(DO*DP) + dp];
            #pragma unroll
            for (int r = 0; r < 4; r++) acc[r] = fmaf(p1s[r][c], wv, acc[r]);
        }
        #pragma unroll
        for (int r = 0; r < 4; r++) g_A[(size_t)(r0 + r)*(DO*DP) + dp] = acc[r];
    }
}

// ---------------- final: z_out = LN(z + A(i)·p2(j) + bz), A in registers ----------------
__global__ void __launch_bounds__(256, 2)
pair_final_kernel(const float* __restrict__ z, const float* __restrict__ bz,
                  const float* __restrict__ g, const float* __restrict__ be,
                  float* __restrict__ zout) {
    int bi = blockIdx.x;
    int b = bi / LL;
    int t = threadIdx.x, w = t >> 5, lane = t & 31;
    const float2* Ag = (const float2*)(g_A + (size_t)bi*(DO*DP));
    float2 a[DO];
    #pragma unroll
    for (int d = 0; d < DO; d++) a[d] = Ag[d*32 + lane];
    float bz0 = bz[2*lane], bz1 = bz[2*lane + 1];
    float g0 = g[2*lane],  g1 = g[2*lane + 1];
    float e0 = be[2*lane], e1 = be[2*lane + 1];
    size_t zbase = (size_t)bi * LL * DP;
    const float* p2b = g_p2 + (size_t)b * LL * DO;
    for (int j = w; j < LL; j += 8) {
        float p2v = p2b[j*DO + lane];
        float2 zv = *(const float2*)(z + zbase + (size_t)j*DP + 2*lane);
        float acc0 = 0.f, acc1 = 0.f;
        #pragma unroll
        for (int d = 0; d < DO; d++) {
            float s = __shfl_sync(0xffffffffu, p2v, d);
            acc0 = fmaf(s, a[d].x, acc0);
            acc1 = fmaf(s, a[d].y, acc1);
        }
        float v0 = zv.x + acc0 + bz0;
        float v1 = zv.y + acc1 + bz1;
        float s1 = warp_sum(v0 + v1);
        float s2 = warp_sum(fmaf(v0, v0, v1*v1));
        float mu = s1 * (1.f/64.f);
        float var = s2 * (1.f/64.f) - mu*mu;
        float rs = rsqrtf(var + 1e-5f);
        float2 o;
        o.x = (v0 - mu) * rs * g0 + e0;
        o.y = (v1 - mu) * rs * g1 + e1;
        *(float2*)(zout + zbase + (size_t)j*DP + 2*lane) = o;
    }
}

extern "C" void kernel_launch(void* const* d_in, const int* in_sizes, int n_in,
                              void* d_out, int out_size) {
    const float* x      = (const float*)d_in[0];
    const float* z      = (const float*)d_in[1];
    const float* Wq     = (const float*)d_in[2];
    const float* Wk     = (const float*)d_in[3];
    const float* Wv     = (const float*)d_in[4];
    const float* Wb     = (const float*)d_in[5];
    const float* Wo     = (const float*)d_in[6];
    const float* bo     = (const float*)d_in[7];
    const float* ln1_g  = (const float*)d_in[8];
    const float* ln1_b  = (const float*)d_in[9];
    const float* W1     = (const float*)d_in[10];
    const float* b1     = (const float*)d_in[11];
    const float* W2     = (const float*)d_in[12];
    const float* b2     = (const float*)d_in[13];
    const float* ln2_g  = (const float*)d_in[14];
    const float* ln2_b  = (const float*)d_in[15];
    const float* Wp1    = (const float*)d_in[16];
    const float* bp1    = (const float*)d_in[17];
    const float* Wp2    = (const float*)d_in[18];
    const float* bp2    = (const float*)d_in[19];
    const float* Wz     = (const float*)d_in[20];
    const float* bz     = (const float*)d_in[21];
    const float* lnp_g  = (const float*)d_in[22];
    const float* lnp_b  = (const float*)d_in[23];

    float* out_x = (float*)d_out;                       // [B,L,D]
    float* out_z = (float*)d_out + (size_t)NROW*DD;     // [B,L,L,DP]

    ln1_qkv_kernel<<<NROW, 128>>>(x, ln1_g, ln1_b, Wq, Wk, Wv);
    bias_kernel<<<NPAIR/32, 256>>>(z, Wb);
    attn_kernel<<<NROW, 256>>>();
    proj_ln2_kernel<<<NROW, 128>>>(x, Wo, bo, ln2_g, ln2_b);
    ffn1_kernel<<<NROW, 256>>>(W1, b1);
    ffn2_pproj_kernel<<<NROW, 128>>>(W2, b2, out_x, Wp1, bp1, Wp2, bp2);
    a_kernel<<<NROW/4, 256>>>(Wz);
    pair_final_kernel<<<NROW, 256>>>(z, bz, lnp_g, lnp_b, out_z);
}

// round 7
// speedup vs baseline: 2.0084x; 1.2093x over previous
#include <cuda_runtime.h>
#include <math.h>

#define BB 2
#define LL 320
#define DD 128
#define DP 64
#define NH 8
#define DH 16
#define DO 32
#define NROW (BB*LL)          // 640
#define NPAIR (BB*LL*LL)      // 204800
#define SCP 321               // padded score row

// ---------------- scratch (allocation-free, device-side references ONLY) ----------------
__device__ float g_q [NROW*DD];
__device__ float g_k [NROW*DD];
__device__ float g_v [NROW*DD];
__device__ float g_bias[NPAIR*NH];     // [b,i,j,h]
__device__ float g_attn[NROW*DD];
__device__ float g_p1[NROW*DO];
__device__ float g_p2[NROW*DO];
__device__ float g_A [NROW*DO*DP];     // [row, d, p]

__device__ __forceinline__ float warp_sum(float v) {
    #pragma unroll
    for (int o = 16; o; o >>= 1) v += __shfl_xor_sync(0xffffffffu, v, o);
    return v;
}
__device__ __forceinline__ float warp_max(float v) {
    #pragma unroll
    for (int o = 16; o; o >>= 1) v = fmaxf(v, __shfl_xor_sync(0xffffffffu, v, o));
    return v;
}

// ---------------- fused ln1 + QKV: 384 threads, one output per thread ----------------
__global__ void __launch_bounds__(384)
ln1_qkv_kernel(const float* __restrict__ x,
               const float* __restrict__ lg, const float* __restrict__ lb,
               const float* __restrict__ Wq, const float* __restrict__ Wk,
               const float* __restrict__ Wv) {
    int row = blockIdx.x, t = threadIdx.x;   // 384
    __shared__ float xs[DD];
    __shared__ float r1[4], r2[4];
    float v = 0.f;
    if (t < DD) {
        v = x[row*DD + t];
        float s = warp_sum(v);
        if ((t & 31) == 0) r1[t >> 5] = s;
    }
    __syncthreads();
    if (t < DD) {
        float mu = (r1[0] + r1[1] + r1[2] + r1[3]) * (1.f/128.f);
        float d = v - mu;
        float sq = warp_sum(d*d);
        if ((t & 31) == 0) r2[t >> 5] = sq;
    }
    __syncthreads();
    if (t < DD) {
        float mu = (r1[0] + r1[1] + r1[2] + r1[3]) * (1.f/128.f);
        float var = (r2[0] + r2[1] + r2[2] + r2[3]) * (1.f/128.f);
        xs[t] = (v - mu) * rsqrtf(var + 1e-5f) * lg[t] + lb[t];
    }
    __syncthreads();
    int c = t & 127, which = t >> 7;   // 0=q, 1=k, 2=v
    const float* W = (which == 0) ? Wq : ((which == 1) ? Wk : Wv);
    float* outp    = (which == 0) ? g_q : ((which == 1) ? g_k : g_v);
    float a0 = 0.f, a1 = 0.f;
    #pragma unroll 8
    for (int kk = 0; kk < DD; kk += 2) {
        a0 = fmaf(xs[kk],   W[kk*DD + c],     a0);
        a1 = fmaf(xs[kk+1], W[(kk+1)*DD + c], a1);
    }
    outp[row*DD + c] = a0 + a1;
}

// ---------------- bias: smem-tiled, one (pair,h) output per thread ----------------
__global__ void bias_kernel(const float* __restrict__ z, const float* __restrict__ Wb) {
    __shared__ __align__(16) float zs[32][68];   // 32 pairs x 64 (+4 pad)
    __shared__ float wbs[DP][NH];                // [p][h]
    int t = threadIdx.x;                         // 256
    wbs[t >> 3][t & 7] = Wb[t];
    { int i2 = t + 256; wbs[i2 >> 3][i2 & 7] = Wb[i2]; }
    size_t base = (size_t)blockIdx.x * 32 * DP;
    const float4* zsrc = (const float4*)(z + base);
    #pragma unroll
    for (int i = 0; i < 2; i++) {
        int idx = t + i*256;
        int pair = idx >> 4, c4 = idx & 15;
        *((float4*)&zs[pair][c4*4]) = zsrc[idx];
    }
    __syncthreads();
    int pair = t >> 3, h = t & 7;
    float a0 = 0.f, a1 = 0.f;
    #pragma unroll
    for (int p = 0; p < DP; p += 2) {
        a0 = fmaf(zs[pair][p],   wbs[p][h],   a0);
        a1 = fmaf(zs[pair][p+1], wbs[p+1][h], a1);
    }
    g_bias[(size_t)blockIdx.x * 256 + t] = a0 + a1;
}

// ---------------- attention: one block per (b,i), V tiled via SMEM ----------------
__global__ void attn_kernel() {
    int bi = blockIdx.x;
    int b = bi / LL;
    int t = threadIdx.x;            // 256
    __shared__ float qs[DD];
    __shared__ float sc[NH*SCP];
    __shared__ float vs[32*DD];
    __shared__ float part[DD];
    if (t < DD) qs[t] = g_q[bi*DD + t];
    __syncthreads();
    for (int idx = t; idx < NH*LL; idx += 256) {
        int h = idx / LL, j = idx - h*LL;
        const float4* kp = (const float4*)(g_k + ((size_t)(b*LL + j))*DD + h*DH);
        const float4* qp = (const float4*)(qs + h*DH);
        float acc = 0.f;
        #pragma unroll
        for (int d4 = 0; d4 < 4; d4++) {
            float4 kv = kp[d4], qv = qp[d4];
            acc = fmaf(qv.x, kv.x, acc);
            acc = fmaf(qv.y, kv.y, acc);
            acc = fmaf(qv.z, kv.z, acc);
            acc = fmaf(qv.w, kv.w, acc);
        }
        sc[h*SCP + j] = acc * 0.25f + g_bias[((size_t)bi*LL + j)*NH + h];
    }
    __syncthreads();
    int w = t >> 5, lane = t & 31;
    float m = -INFINITY;
    for (int j = lane; j < LL; j += 32) m = fmaxf(m, sc[w*SCP + j]);
    m = warp_max(m);
    float s = 0.f;
    for (int j = lane; j < LL; j += 32) {
        float e = __expf(sc[w*SCP + j] - m);
        sc[w*SCP + j] = e;
        s += e;
    }
    s = warp_sum(s);
    float inv = 1.f / s;
    for (int j = lane; j < LL; j += 32) sc[w*SCP + j] *= inv;
    __syncthreads();
    int c = t & 127, half = t >> 7;
    int h = c >> 4;
    float acc = 0.f;
    int jb = half * 16;
    for (int j0 = 0; j0 < LL; j0 += 32) {
        const float4* vsrc = (const float4*)(g_v + ((size_t)(b*LL + j0))*DD);
        float4* vdst = (float4*)vs;
        #pragma unroll
        for (int i = 0; i < 4; i++) vdst[t + i*256] = vsrc[t + i*256];
        __syncthreads();
        #pragma unroll
        for (int jj = 0; jj < 16; jj++)
            acc = fmaf(sc[h*SCP + j0 + jb + jj], vs[(jb + jj)*DD + c], acc);
        __syncthreads();
    }
    if (half == 1) part[c] = acc;
    __syncthreads();
    if (half == 0) g_attn[bi*DD + c] = acc + part[c];
}

// ---------------- mega row kernel: proj + ln2 + ffn1 + ffn2 + pproj ----------------
__global__ void __launch_bounds__(512)
mega_row_kernel(const float* __restrict__ x,
                const float* __restrict__ Wo, const float* __restrict__ bo,
                const float* __restrict__ lg2, const float* __restrict__ lb2,
                const float* __restrict__ W1, const float* __restrict__ b1,
                const float* __restrict__ W2, const float* __restrict__ b2,
                float* __restrict__ out_x,
                const float* __restrict__ Wp1, const float* __restrict__ bp1,
                const float* __restrict__ Wp2, const float* __restrict__ bp2) {
    int row = blockIdx.x, t = threadIdx.x;   // 512
    __shared__ float as[DD];
    __shared__ float xs[DD];
    __shared__ float hs[512];
    __shared__ float part[4][DD];
    __shared__ float r1[4], r2[4];

    if (t < DD) as[t] = g_attn[row*DD + t];
    __syncthreads();

    // --- proj: split-K4 ---
    int c = t & 127, ks = t >> 7;            // ks in 0..3
    {
        int k0 = ks*32;
        float a0 = 0.f, a1 = 0.f;
        #pragma unroll
        for (int kk = 0; kk < 32; kk += 2) {
            a0 = fmaf(as[k0+kk],   Wo[(k0+kk)*DD + c],   a0);
            a1 = fmaf(as[k0+kk+1], Wo[(k0+kk+1)*DD + c], a1);
        }
        part[ks][c] = a0 + a1;
    }
    __syncthreads();

    // --- residual + ln2 (threads 0..127; warps 0-3 fully active) ---
    float v = 0.f;
    if (t < DD) {
        v = x[row*DD + t] + part[0][t] + part[1][t] + part[2][t] + part[3][t] + bo[t];
        float s = warp_sum(v);
        if ((t & 31) == 0) r1[t >> 5] = s;
    }
    __syncthreads();
    if (t < DD) {
        float mu = (r1[0] + r1[1] + r1[2] + r1[3]) * (1.f/128.f);
        float d = v - mu;
        float sq = warp_sum(d*d);
        if ((t & 31) == 0) r2[t >> 5] = sq;
    }
    __syncthreads();
    if (t < DD) {
        float mu = (r1[0] + r1[1] + r1[2] + r1[3]) * (1.f/128.f);
        float var = (r2[0] + r2[1] + r2[2] + r2[3]) * (1.f/128.f);
        xs[t] = (v - mu) * rsqrtf(var + 1e-5f) * lg2[t] + lb2[t];
    }
    __syncthreads();

    // --- ffn1: one output per thread (512 cols) ---
    {
        float a0 = 0.f, a1 = 0.f;
        #pragma unroll 8
        for (int kk = 0; kk < DD; kk += 2) {
            a0 = fmaf(xs[kk],   W1[kk*512 + t],     a0);
            a1 = fmaf(xs[kk+1], W1[(kk+1)*512 + t], a1);
        }
        float hv = a0 + a1 + b1[t];
        hs[t] = 0.5f * hv * (1.f + erff(hv * 0.70710678118654752f));
    }
    __syncthreads();

    // --- ffn2: split-K4 (each slice 128 of 512) ---
    {
        int k0 = ks*128;
        float a0 = 0.f, a1 = 0.f;
        #pragma unroll 8
        for (int kk = 0; kk < 128; kk += 2) {
            a0 = fmaf(hs[k0+kk],   W2[(k0+kk)*DD + c],   a0);
            a1 = fmaf(hs[k0+kk+1], W2[(k0+kk+1)*DD + c], a1);
        }
        part[ks][c] = a0 + a1;
    }
    __syncthreads();
    if (t < DD) {
        float xv = v + part[0][t] + part[1][t] + part[2][t] + part[3][t] + b2[t];
        out_x[row*DD + t] = xv;
        xs[t] = xv;
    }
    __syncthreads();

    // --- pproj: 64 outputs (32 p1 + 32 p2), split-K4 with 256 threads ---
    if (t < 256) {
        int o  = t & 63;           // 0..31 -> p1, 32..63 -> p2
        int sl = t >> 6;           // 0..3
        const float* W = (o < 32) ? Wp1 : Wp2;
        int col = o & 31;
        int k0 = sl*32;
        float a0 = 0.f, a1 = 0.f;
        #pragma unroll
        for (int kk = 0; kk < 32; kk += 2) {
            a0 = fmaf(xs[k0+kk],   W[(k0+kk)*DO + col],   a0);
            a1 = fmaf(xs[k0+kk+1], W[(k0+kk+1)*DO + col], a1);
        }
        part[sl][o] = a0 + a1;
    }
    __syncthreads();
    if (t < 64) {
        float sum = part[0][t] + part[1][t] + part[2][t] + part[3][t];
        if (t < 32) g_p1[row*DO + t]        = sum + bp1[t];
        else        g_p2[row*DO + (t - 32)] = sum + bp2[t - 32];
    }
}

// ---------------- A[row, d, p] = sum_c p1[row,c] * Wz[(c*32+d)*64+p] ----------------
__global__ void a_kernel(const float* __restrict__ Wz) {
    int r0 = blockIdx.x * 4;
    int t = threadIdx.x;              // 256
    __shared__ float p1s[4][DO];
    if (t < 128) { int r = t >> 5, c = t & 31; p1s[r][c] = g_p1[(r0 + r)*DO + c]; }
    __syncthreads();
    for (int dp = t; dp < DO*DP; dp += 256) {
        float acc[4] = {0,0,0,0};
        #pragma unroll 8
        for (int c = 0; c < DO; c++) {
            float wv = Wz[(size_t)c*(DO*DP) + dp];
            #pragma unroll
            for (int r = 0; r < 4; r++) acc[r] = fmaf(p1s[r][c], wv, acc[r]);
        }
        #pragma unroll
        for (int r = 0; r < 4; r++) g_A[(size_t)(r0 + r)*(DO*DP) + dp] = acc[r];
    }
}

// ---------------- final: z_out = LN(z + A(i)·p2(j) + bz) ----------------
// A in registers; p2 staged in smem tiles, read via float4 broadcast (no shfl broadcast loop)
__global__ void __launch_bounds__(256, 2)
pair_final_kernel(const float* __restrict__ z, const float* __restrict__ bz,
                  const float* __restrict__ g, const float* __restrict__ be,
                  float* __restrict__ zout) {
    int bi = blockIdx.x;
    int b = bi / LL;
    int t = threadIdx.x, w = t >> 5, lane = t & 31;
    __shared__ __align__(16) float p2s[64][DO];   // 8 KB tile
    const float2* Ag = (const float2*)(g_A + (size_t)bi*(DO*DP));
    float2 a[DO];
    #pragma unroll
    for (int d = 0; d < DO; d++) a[d] = Ag[d*32 + lane];
    float bz0 = bz[2*lane], bz1 = bz[2*lane + 1];
    float g0 = g[2*lane],  g1 = g[2*lane + 1];
    float e0 = be[2*lane], e1 = be[2*lane + 1];
    size_t zbase = (size_t)bi * LL * DP;
    const float* p2b = g_p2 + (size_t)b * LL * DO;
    for (int jt = 0; jt < LL; jt += 64) {
        // stage 64 p2 rows (2048 floats = 512 float4) via 256 threads
        const float4* src = (const float4*)(p2b + (size_t)jt * DO);
        float4* dst = (float4*)&p2s[0][0];
        dst[t] = src[t];
        dst[t + 256] = src[t + 256];
        __syncthreads();
        for (int jj = w; jj < 64; jj += 8) {
            int j = jt + jj;
            float2 zv = *(const float2*)(z + zbase + (size_t)j*DP + 2*lane);
            const float4* p4 = (const float4*)&p2s[jj][0];
            float acc0 = 0.f, acc1 = 0.f;
            #pragma unroll
            for (int d4 = 0; d4 < 8; d4++) {
                float4 s4 = p4[d4];
                acc0 = fmaf(s4.x, a[d4*4+0].x, acc0); acc1 = fmaf(s4.x, a[d4*4+0].y, acc1);
                acc0 = fmaf(s4.y, a[d4*4+1].x, acc0); acc1 = fmaf(s4.y, a[d4*4+1].y, acc1);
                acc0 = fmaf(s4.z, a[d4*4+2].x, acc0); acc1 = fmaf(s4.z, a[d4*4+2].y, acc1);
                acc0 = fmaf(s4.w, a[d4*4+3].x, acc0); acc1 = fmaf(s4.w, a[d4*4+3].y, acc1);
            }
            float v0 = zv.x + acc0 + bz0;
            float v1 = zv.y + acc1 + bz1;
            float s1 = warp_sum(v0 + v1);
            float s2 = warp_sum(fmaf(v0, v0, v1*v1));
            float mu = s1 * (1.f/64.f);
            float var = s2 * (1.f/64.f) - mu*mu;
            float rs = rsqrtf(var + 1e-5f);
            float2 o;
            o.x = (v0 - mu) * rs * g0 + e0;
            o.y = (v1 - mu) * rs * g1 + e1;
            *(float2*)(zout + zbase + (size_t)j*DP + 2*lane) = o;
        }
        __syncthreads();
    }
}

extern "C" void kernel_launch(void* const* d_in, const int* in_sizes, int n_in,
                              void* d_out, int out_size) {
    const float* x      = (const float*)d_in[0];
    const float* z      = (const float*)d_in[1];
    const float* Wq     = (const float*)d_in[2];
    const float* Wk     = (const float*)d_in[3];
    const float* Wv     = (const float*)d_in[4];
    const float* Wb     = (const float*)d_in[5];
    const float* Wo     = (const float*)d_in[6];
    const float* bo     = (const float*)d_in[7];
    const float* ln1_g  = (const float*)d_in[8];
    const float* ln1_b  = (const float*)d_in[9];
    const float* W1     = (const float*)d_in[10];
    const float* b1     = (const float*)d_in[11];
    const float* W2     = (const float*)d_in[12];
    const float* b2     = (const float*)d_in[13];
    const float* ln2_g  = (const float*)d_in[14];
    const float* ln2_b  = (const float*)d_in[15];
    const float* Wp1    = (const float*)d_in[16];
    const float* bp1    = (const float*)d_in[17];
    const float* Wp2    = (const float*)d_in[18];
    const float* bp2    = (const float*)d_in[19];
    const float* Wz     = (const float*)d_in[20];
    const float* bz     = (const float*)d_in[21];
    const float* lnp_g  = (const float*)d_in[22];
    const float* lnp_b  = (const float*)d_in[23];

    float* out_x = (float*)d_out;                       // [B,L,D]
    float* out_z = (float*)d_out + (size_t)NROW*DD;     // [B,L,L,DP]

    ln1_qkv_kernel<<<NROW, 384>>>(x, ln1_g, ln1_b, Wq, Wk, Wv);
    bias_kernel<<<NPAIR/32, 256>>>(z, Wb);
    attn_kernel<<<NROW, 256>>>();
    mega_row_kernel<<<NROW, 512>>>(x, Wo, bo, ln2_g, ln2_b, W1, b1, W2, b2,
                                   out_x, Wp1, bp1, Wp2, bp2);
    a_kernel<<<NROW/4, 256>>>(Wz);
    pair_final_kernel<<<NROW, 256>>>(z, bz, lnp_g, lnp_b, out_z);
}